// round 8
// baseline (speedup 1.0000x reference)
#include <cuda_runtime.h>
#include <cuda_bf16.h>
#include <math_constants.h>

#define B 16
#define F 1024
#define H 16
#define D 64
#define L 8192
#define HD 1024            // H*D
#define NFC 32             // f-chunks for qkv split-K partials (chunk = 32)
#define NOC 64             // hd-chunks for out-proj partials (chunk = 16)
#define NSPLIT 8
#define CHUNK_L 1024

// -------- device scratch (allocation-free: __device__ globals) --------
__device__ float g_qkv_part[3 * NFC * B * HD];      // 6 MB
__device__ float g_qkv[3 * B * HD];                 // q,k,v fp32
__device__ float g_logits[B * H * L];               // 8 MB fp32 logits
__device__ float g_cmax[B * H * NSPLIT];
__device__ float g_m[B * H];
__device__ float g_s[B * H];
__device__ float g_accpart[B * H * NSPLIT * D];     // split partial AV sums
__device__ float g_attn[B * HD];                    // bf16-rounded attn, fp32
__device__ float g_o_part[NOC * B * F];             // 4 MB

__device__ __forceinline__ float bfr(float v) {
    // round-to-nearest-even through bf16, back to fp32 (matches astype(bf16))
    return __bfloat162float(__float2bfloat16(v));
}

// -------- QKV projection: split-K partial GEMV --------
// grid (NFC, 3), 256 threads. Each thread: 4 output cols x 16 batches.
__global__ __launch_bounds__(256) void qkv_partial_k(
        const float* __restrict__ x,
        const float* __restrict__ Wq, const float* __restrict__ Wk,
        const float* __restrict__ Wv) {
    const int fc = blockIdx.x, w = blockIdx.y;
    const float* Wt = (w == 0) ? Wq : ((w == 1) ? Wk : Wv);
    const int f0 = fc * (F / NFC);
    __shared__ float xs[F / NFC][B];
    const int tid = threadIdx.x;
    for (int i = tid; i < (F / NFC) * B; i += 256) {
        int f = i >> 4, b = i & 15;
        xs[f][b] = x[b * F + f0 + f];
    }
    __syncthreads();
    float4 acc[B];
#pragma unroll
    for (int b = 0; b < B; b++) acc[b] = make_float4(0.f, 0.f, 0.f, 0.f);
    const float4* wp = reinterpret_cast<const float4*>(Wt + (size_t)f0 * HD) + tid;
#pragma unroll 4
    for (int f = 0; f < F / NFC; f++) {
        float4 w4 = wp[(size_t)f * (HD / 4)];
#pragma unroll
        for (int b = 0; b < B; b++) {
            float xb = xs[f][b];
            acc[b].x = fmaf(xb, w4.x, acc[b].x);
            acc[b].y = fmaf(xb, w4.y, acc[b].y);
            acc[b].z = fmaf(xb, w4.z, acc[b].z);
            acc[b].w = fmaf(xb, w4.w, acc[b].w);
        }
    }
    float* dst = g_qkv_part + (size_t)(w * NFC + fc) * B * HD;
#pragma unroll
    for (int b = 0; b < B; b++)
        reinterpret_cast<float4*>(dst + b * HD)[tid] = acc[b];
}

// Reduce partials + bias; scatter k_new/v_new into output caches; write new_idx.
// NOTE: new_idx is written as FLOAT — harness output buffer is float32 dtype.
__global__ __launch_bounds__(256) void qkv_reduce_k(
        const float* __restrict__ bq, const float* __restrict__ bk,
        const float* __restrict__ bv, const int* __restrict__ kvidx,
        float* __restrict__ okey, float* __restrict__ oval,
        float* __restrict__ oidx) {
    int g = blockIdx.x * 256 + threadIdx.x;      // < 3*B*HD = 49152
    int w = g >> 14;
    int r = g & 16383;
    int b = r >> 10;
    int col = r & 1023;
    float s = 0.f;
#pragma unroll 8
    for (int c = 0; c < NFC; c++)
        s += g_qkv_part[(size_t)(w * NFC + c) * B * HD + b * HD + col];
    const float* bias = (w == 0) ? bq : ((w == 1) ? bk : bv);
    s += bias[col];
    g_qkv[(w * B + b) * HD + col] = s;
    int kvi = kvidx[b];
    int slot = kvi % L; if (slot < 0) slot += L;
    if (w == 1)       okey[((size_t)b * L + slot) * HD + col] = s;
    else if (w == 2)  oval[((size_t)b * L + slot) * HD + col] = s;
    else if (col == 0) oidx[b] = (float)(kvi + 1);
}

// -------- attention phase 1: logits (bf16 inputs, fp32 accumulate) --------
// grid (NSPLIT, H, B), 256 threads; warp per l, lane per 2 d.
__global__ __launch_bounds__(256) void attn_logits_k(
        const float* __restrict__ okey, const int* __restrict__ kvidx) {
    const int b = blockIdx.z, h = blockIdx.y, sp = blockIdx.x;
    const int seq = min(kvidx[b] + 1, L);
    const int l0 = sp * CHUNK_L;
    const int lend = min(l0 + CHUNK_L, seq);
    const int warp = threadIdx.x >> 5, lane = threadIdx.x & 31;
    const int d0 = lane * 2;
    __shared__ float wmax[8];
    float mloc = -CUDART_INF_F;
    if (l0 < lend) {
        const float q0 = bfr(g_qkv[b * HD + h * D + d0]);
        const float q1 = bfr(g_qkv[b * HD + h * D + d0 + 1]);
        const float* kp = okey + (size_t)b * L * HD + h * D + d0;
        float* lrow = g_logits + (size_t)(b * H + h) * L;
#pragma unroll 2
        for (int l = l0 + warp; l < lend; l += 8) {
            float2 k2 = *reinterpret_cast<const float2*>(kp + (size_t)l * HD);
            float s = bfr(k2.x) * q0 + bfr(k2.y) * q1;
#pragma unroll
            for (int off = 16; off; off >>= 1)
                s += __shfl_down_sync(0xffffffffu, s, off);
            if (lane == 0) {
                float lg = s * 0.125f;   // 1/sqrt(64)
                lrow[l] = lg;
                mloc = fmaxf(mloc, lg);
            }
        }
    }
    if (lane == 0) wmax[warp] = mloc;
    __syncthreads();
    if (threadIdx.x == 0) {
        float m = wmax[0];
#pragma unroll
        for (int i = 1; i < 8; i++) m = fmaxf(m, wmax[i]);
        g_cmax[(b * H + h) * NSPLIT + sp] = m;
    }
}

// -------- softmax stats: global max + sum(exp) per (b,h) --------
__global__ __launch_bounds__(256) void attn_stats_k(const int* __restrict__ kvidx) {
    const int bh = blockIdx.x;
    const int b = bh >> 4;
    const int seq = min(kvidx[b] + 1, L);
    const int nch = (seq + CHUNK_L - 1) / CHUNK_L;
    float m = -CUDART_INF_F;
    for (int c = 0; c < nch; c++) m = fmaxf(m, g_cmax[bh * NSPLIT + c]);
    const float* lrow = g_logits + (size_t)bh * L;
    float sum = 0.f;
    for (int l = threadIdx.x; l < seq; l += 256) sum += expf(lrow[l] - m);
    __shared__ float red[256];
    red[threadIdx.x] = sum;
    __syncthreads();
    for (int st = 128; st; st >>= 1) {
        if (threadIdx.x < st) red[threadIdx.x] += red[threadIdx.x + st];
        __syncthreads();
    }
    if (threadIdx.x == 0) { g_m[bh] = m; g_s[bh] = red[0]; }
}

// -------- attention phase 2: probs(bf16) . V(bf16), fp32 accumulate --------
__global__ __launch_bounds__(256) void attn_av_k(
        const float* __restrict__ oval, const int* __restrict__ kvidx) {
    const int b = blockIdx.z, h = blockIdx.y, sp = blockIdx.x;
    const int bh = b * H + h;
    const int seq = min(kvidx[b] + 1, L);
    const int l0 = sp * CHUNK_L;
    const int lend = min(l0 + CHUNK_L, seq);
    const int warp = threadIdx.x >> 5, lane = threadIdx.x & 31;
    const int d0 = lane * 2;
    float ax = 0.f, ay = 0.f;
    if (l0 < lend) {
        const float m = g_m[bh];
        const float den = g_s[bh];
        const float* vp = oval + (size_t)b * L * HD + h * D + d0;
        const float* lrow = g_logits + (size_t)bh * L;
#pragma unroll 2
        for (int l = l0 + warp; l < lend; l += 8) {
            float p = expf(lrow[l] - m) / den;     // fp32 softmax like the ref
            float pb = bfr(p);                     // probs.astype(bf16)
            float2 v2 = *reinterpret_cast<const float2*>(vp + (size_t)l * HD);
            ax = fmaf(pb, bfr(v2.x), ax);
            ay = fmaf(pb, bfr(v2.y), ay);
        }
    }
    __shared__ float sacc[8][64];
    sacc[warp][d0] = ax;
    sacc[warp][d0 + 1] = ay;
    __syncthreads();
    if (threadIdx.x < 64) {
        float t = 0.f;
#pragma unroll
        for (int w = 0; w < 8; w++) t += sacc[w][threadIdx.x];
        g_accpart[((size_t)bh * NSPLIT + sp) * D + threadIdx.x] = t;
    }
}

// Combine splits, round to bf16 (einsum output dtype), keep fp32.
__global__ __launch_bounds__(256) void attn_combine_k() {
    int g = blockIdx.x * 256 + threadIdx.x;   // < B*HD = 16384, g = bh*64 + d
    int bh = g >> 6, d = g & 63;
    float t = 0.f;
#pragma unroll
    for (int sp = 0; sp < NSPLIT; sp++)
        t += g_accpart[((size_t)bh * NSPLIT + sp) * D + d];
    g_attn[g] = bfr(t);
}

// -------- output projection: split-K partial GEMV over hd --------
__global__ __launch_bounds__(256) void oproj_partial_k(const float* __restrict__ Wo) {
    const int c = blockIdx.x;
    const int hd0 = c * (HD / NOC);    // chunk = 16
    __shared__ float xs[HD / NOC][B];
    const int tid = threadIdx.x;
    { int f = tid >> 4, b = tid & 15; xs[f][b] = g_attn[b * HD + hd0 + f]; }
    __syncthreads();
    float4 acc[B];
#pragma unroll
    for (int b = 0; b < B; b++) acc[b] = make_float4(0.f, 0.f, 0.f, 0.f);
    const float4* wp = reinterpret_cast<const float4*>(Wo + (size_t)hd0 * F) + tid;
#pragma unroll
    for (int f = 0; f < HD / NOC; f++) {
        float4 w4 = wp[(size_t)f * (F / 4)];
#pragma unroll
        for (int b = 0; b < B; b++) {
            float xb = xs[f][b];
            acc[b].x = fmaf(xb, w4.x, acc[b].x);
            acc[b].y = fmaf(xb, w4.y, acc[b].y);
            acc[b].z = fmaf(xb, w4.z, acc[b].z);
            acc[b].w = fmaf(xb, w4.w, acc[b].w);
        }
    }
    float* dst = g_o_part + (size_t)c * B * F;
#pragma unroll
    for (int b = 0; b < B; b++)
        reinterpret_cast<float4*>(dst + b * F)[tid] = acc[b];
}

__global__ __launch_bounds__(256) void oproj_reduce_k(
        const float* __restrict__ bo, float* __restrict__ y) {
    int g = blockIdx.x * 256 + threadIdx.x;   // < B*F = 16384
    int b = g >> 10, col = g & 1023;
    float s = 0.f;
#pragma unroll 8
    for (int c = 0; c < NOC; c++)
        s += g_o_part[(size_t)c * B * F + b * F + col];
    y[g] = s + bo[col];
}

// -------- launch --------
extern "C" void kernel_launch(void* const* d_in, const int* in_sizes, int n_in,
                              void* d_out, int out_size) {
    (void)in_sizes; (void)n_in; (void)out_size;
    const float* x    = (const float*)d_in[0];
    const float* kk   = (const float*)d_in[1];
    const float* kv   = (const float*)d_in[2];
    const int*   kvix = (const int*)  d_in[3];
    const float* Wq   = (const float*)d_in[4];
    const float* bq   = (const float*)d_in[5];
    const float* Wk   = (const float*)d_in[6];
    const float* bk   = (const float*)d_in[7];
    const float* Wv   = (const float*)d_in[8];
    const float* bv   = (const float*)d_in[9];
    const float* Wo   = (const float*)d_in[10];
    const float* bo   = (const float*)d_in[11];

    // Output layout (all float32): y[B*F], kv_key[B*L*H*D], kv_value[B*L*H*D],
    // new_idx[B] stored as float.
    float* out  = (float*)d_out;
    float* y    = out;
    float* okey = out + (size_t)B * F;
    float* oval = okey + (size_t)B * L * HD;
    float* oidx = oval + (size_t)B * L * HD;

    const size_t cache_bytes = (size_t)B * L * HD * sizeof(float);
    cudaMemcpyAsync(okey, kk, cache_bytes, cudaMemcpyDeviceToDevice, 0);
    cudaMemcpyAsync(oval, kv, cache_bytes, cudaMemcpyDeviceToDevice, 0);

    qkv_partial_k<<<dim3(NFC, 3), 256>>>(x, Wq, Wk, Wv);
    qkv_reduce_k<<<(3 * B * HD) / 256, 256>>>(bq, bk, bv, kvix, okey, oval, oidx);
    attn_logits_k<<<dim3(NSPLIT, H, B), 256>>>(okey, kvix);
    attn_stats_k<<<B * H, 256>>>(kvix);
    attn_av_k<<<dim3(NSPLIT, H, B), 256>>>(oval, kvix);
    attn_combine_k<<<(B * HD) / 256, 256>>>();
    oproj_partial_k<<<NOC, 256>>>(Wo);
    oproj_reduce_k<<<(B * F) / 256, 256>>>(bo, y);
}

// round 10
// speedup vs baseline: 2.3531x; 2.3531x over previous
#include <cuda_runtime.h>
#include <cuda_bf16.h>
#include <math_constants.h>

#define B 16
#define F 1024
#define H 16
#define D 64
#define L 8192
#define HD 1024            // H*D
#define NFC 32             // f-chunks for qkv split-K partials
#define NOC 64             // hd-chunks for out-proj partials
#define TBK 64             // K rows per block in fused K kernel
#define TBV 128            // V rows per block in fused V kernel
#define NCV (L / TBV)      // 64 chunks per batch

// -------- device scratch (allocation-free: __device__ globals) --------
__device__ float g_qkv_part[3 * NFC * B * HD];      // 6 MB
__device__ float g_qkv[3 * B * HD];                 // q,k,v fp32 (+bias)
__device__ float g_logits[B * H * L];               // 8 MB fp32 logits
__device__ float g_m[B * H];
__device__ float g_s[B * H];
__device__ float g_accpart[B * H * NCV * D];        // 4 MB split AV partials
__device__ float g_attn[B * HD];                    // bf16-rounded attn, fp32
__device__ float g_o_part[NOC * B * F];             // 4 MB

__device__ __forceinline__ float bfr(float v) {
    // round-to-nearest-even through bf16, back to fp32 (matches astype(bf16))
    return __bfloat162float(__float2bfloat16(v));
}

// -------- QKV projection: split-K partial GEMV --------
__global__ __launch_bounds__(256) void qkv_partial_k(
        const float* __restrict__ x,
        const float* __restrict__ Wq, const float* __restrict__ Wk,
        const float* __restrict__ Wv) {
    const int fc = blockIdx.x, w = blockIdx.y;
    const float* Wt = (w == 0) ? Wq : ((w == 1) ? Wk : Wv);
    const int f0 = fc * (F / NFC);
    __shared__ float xs[F / NFC][B];
    const int tid = threadIdx.x;
    for (int i = tid; i < (F / NFC) * B; i += 256) {
        int f = i >> 4, b = i & 15;
        xs[f][b] = x[b * F + f0 + f];
    }
    __syncthreads();
    float4 acc[B];
#pragma unroll
    for (int b = 0; b < B; b++) acc[b] = make_float4(0.f, 0.f, 0.f, 0.f);
    const float4* wp = reinterpret_cast<const float4*>(Wt + (size_t)f0 * HD) + tid;
#pragma unroll 4
    for (int f = 0; f < F / NFC; f++) {
        float4 w4 = wp[(size_t)f * (HD / 4)];
#pragma unroll
        for (int b = 0; b < B; b++) {
            float xb = xs[f][b];
            acc[b].x = fmaf(xb, w4.x, acc[b].x);
            acc[b].y = fmaf(xb, w4.y, acc[b].y);
            acc[b].z = fmaf(xb, w4.z, acc[b].z);
            acc[b].w = fmaf(xb, w4.w, acc[b].w);
        }
    }
    float* dst = g_qkv_part + (size_t)(w * NFC + fc) * B * HD;
#pragma unroll
    for (int b = 0; b < B; b++)
        reinterpret_cast<float4*>(dst + b * HD)[tid] = acc[b];
}

// Reduce partials + bias into g_qkv; write new_idx (as float — output dtype).
__global__ __launch_bounds__(256) void qkv_reduce_k(
        const float* __restrict__ bq, const float* __restrict__ bk,
        const float* __restrict__ bv, const int* __restrict__ kvidx,
        float* __restrict__ oidx) {
    int g = blockIdx.x * 256 + threadIdx.x;      // < 3*B*HD = 49152
    int w = g >> 14;
    int r = g & 16383;
    int b = r >> 10;
    int col = r & 1023;
    float s = 0.f;
#pragma unroll 8
    for (int c = 0; c < NFC; c++)
        s += g_qkv_part[(size_t)(w * NFC + c) * B * HD + b * HD + col];
    const float* bias = (w == 0) ? bq : ((w == 1) ? bk : bv);
    g_qkv[(w * B + b) * HD + col] = s + bias[col];
    if (w == 0 && col == 0) oidx[b] = (float)(kvidx[b] + 1);
}

// -------- fused K: cache copy + slot scatter + logits, one HBM pass --------
// grid = B * (L/TBK) blocks, 256 threads. Thread tid owns head h=tid/16,
// d-range (tid%16)*4..+3 of every 4KB row. Logits computed for ALL rows
// (beyond-seq rows produce unused garbage; inputs are finite so no NaN risk).
__global__ __launch_bounds__(256) void fused_k_kernel(
        const float* __restrict__ kk, const int* __restrict__ kvidx,
        float* __restrict__ okey) {
    const int blk = blockIdx.x;
    const int b = blk / (L / TBK);
    const int l0 = (blk % (L / TBK)) * TBK;
    const int tid = threadIdx.x;
    const int h = tid >> 4;
    const int dq = (tid & 15) * 4;
    const int slot = kvidx[b] % L;

    const float* qp = g_qkv + b * HD + h * D + dq;
    const float q0 = bfr(qp[0]), q1 = bfr(qp[1]), q2 = bfr(qp[2]), q3 = bfr(qp[3]);

    __shared__ float slog[H][TBK + 1];

    const float4* src = reinterpret_cast<const float4*>(
        kk + ((size_t)b * L + l0) * HD) + tid;
    float4* dst = reinterpret_cast<float4*>(
        okey + ((size_t)b * L + l0) * HD) + tid;
    const float4 knew = reinterpret_cast<const float4*>(
        g_qkv + (size_t)(B + b) * HD)[tid];

#pragma unroll 4
    for (int r = 0; r < TBK; r++) {
        float4 k4 = (l0 + r == slot) ? knew : src[(size_t)r * (HD / 4)];
        dst[(size_t)r * (HD / 4)] = k4;
        float s = bfr(k4.x) * q0 + bfr(k4.y) * q1 + bfr(k4.z) * q2 + bfr(k4.w) * q3;
        s += __shfl_down_sync(0xffffffffu, s, 8, 16);
        s += __shfl_down_sync(0xffffffffu, s, 4, 16);
        s += __shfl_down_sync(0xffffffffu, s, 2, 16);
        s += __shfl_down_sync(0xffffffffu, s, 1, 16);
        if ((tid & 15) == 0) slog[h][r] = s * 0.125f;   // 1/sqrt(64)
    }
    __syncthreads();
    // write this block's logits: head h gets contiguous [l0, l0+TBK)
    float4 o;
    o.x = slog[h][dq]; o.y = slog[h][dq + 1];
    o.z = slog[h][dq + 2]; o.w = slog[h][dq + 3];
    *reinterpret_cast<float4*>(g_logits + (size_t)(b * H + h) * L + l0 + dq) = o;
}

// -------- softmax stats: two-pass max + sum(exp) per (b,h) --------
__global__ __launch_bounds__(256) void attn_stats_k(const int* __restrict__ kvidx) {
    const int bh = blockIdx.x;
    const int b = bh >> 4;
    const int seq = min(kvidx[b] + 1, L);
    const float* lrow = g_logits + (size_t)bh * L;
    const int tid = threadIdx.x;
    __shared__ float red[256];

    float m = -CUDART_INF_F;
    for (int l = tid; l < seq; l += 256) m = fmaxf(m, lrow[l]);
    red[tid] = m;
    __syncthreads();
    for (int st = 128; st; st >>= 1) {
        if (tid < st) red[tid] = fmaxf(red[tid], red[tid + st]);
        __syncthreads();
    }
    m = red[0];
    __syncthreads();

    float sum = 0.f;
    for (int l = tid; l < seq; l += 256) sum += expf(lrow[l] - m);
    red[tid] = sum;
    __syncthreads();
    for (int st = 128; st; st >>= 1) {
        if (tid < st) red[tid] += red[tid + st];
        __syncthreads();
    }
    if (tid == 0) { g_m[bh] = m; g_s[bh] = red[0]; }
}

// -------- fused V: cache copy + slot scatter + AV accumulate, one pass ----
// grid = B * NCV blocks, 256 threads. Probs precomputed to smem (zero beyond
// seq so the row loop is branch-free). 256 threads fill H*TBV=2048 entries,
// 8 per thread (fixes R8 OOB: pb is [16][128], tid must not index col>127).
__global__ __launch_bounds__(256) void fused_v_kernel(
        const float* __restrict__ kv, const int* __restrict__ kvidx,
        float* __restrict__ oval) {
    const int blk = blockIdx.x;
    const int b = blk / NCV;
    const int c = blk % NCV;
    const int l0 = c * TBV;
    const int tid = threadIdx.x;
    const int h = tid >> 4;
    const int dq = (tid & 15) * 4;
    const int seq = min(kvidx[b] + 1, L);
    const int slot = kvidx[b] % L;
    const int nvalid = min(TBV, seq - l0);           // may be <= 0

    __shared__ float pb[H][TBV];                      // 8 KB
#pragma unroll
    for (int i = 0; i < (H * TBV) / 256; i++) {
        int lin = tid + 256 * i;        // < 2048
        int k = lin >> 7;               // head 0..15
        int r = lin & (TBV - 1);        // row  0..127
        float p = 0.f;
        if (r < nvalid) {
            const int bhk = b * H + k;
            float lg = g_logits[(size_t)bhk * L + l0 + r];
            p = bfr(expf(lg - g_m[bhk]) / g_s[bhk]);   // probs.astype(bf16)
        }
        pb[k][r] = p;
    }
    __syncthreads();

    const float4* src = reinterpret_cast<const float4*>(
        kv + ((size_t)b * L + l0) * HD) + tid;
    float4* dst = reinterpret_cast<float4*>(
        oval + ((size_t)b * L + l0) * HD) + tid;
    const float4 vnew = reinterpret_cast<const float4*>(
        g_qkv + (size_t)(2 * B + b) * HD)[tid];

    float4 acc = make_float4(0.f, 0.f, 0.f, 0.f);
#pragma unroll 4
    for (int r = 0; r < TBV; r++) {
        float4 v4 = (l0 + r == slot) ? vnew : src[(size_t)r * (HD / 4)];
        dst[(size_t)r * (HD / 4)] = v4;
        float p = pb[h][r];
        acc.x = fmaf(p, bfr(v4.x), acc.x);
        acc.y = fmaf(p, bfr(v4.y), acc.y);
        acc.z = fmaf(p, bfr(v4.z), acc.z);
        acc.w = fmaf(p, bfr(v4.w), acc.w);
    }
    *reinterpret_cast<float4*>(
        g_accpart + ((size_t)(b * H + h) * NCV + c) * D + dq) = acc;
}

// Combine chunk partials, round to bf16 (einsum output dtype), keep fp32.
__global__ __launch_bounds__(256) void attn_combine_k() {
    int g = blockIdx.x * 256 + threadIdx.x;   // < B*HD, g = bh*64 + d
    int bh = g >> 6, d = g & 63;
    float t = 0.f;
#pragma unroll 8
    for (int c = 0; c < NCV; c++)
        t += g_accpart[((size_t)bh * NCV + c) * D + d];
    g_attn[g] = bfr(t);
}

// -------- output projection: split-K partial GEMV over hd --------
__global__ __launch_bounds__(256) void oproj_partial_k(const float* __restrict__ Wo) {
    const int c = blockIdx.x;
    const int hd0 = c * (HD / NOC);    // chunk = 16
    __shared__ float xs[HD / NOC][B];
    const int tid = threadIdx.x;
    { int f = tid >> 4, b = tid & 15; xs[f][b] = g_attn[b * HD + hd0 + f]; }
    __syncthreads();
    float4 acc[B];
#pragma unroll
    for (int b = 0; b < B; b++) acc[b] = make_float4(0.f, 0.f, 0.f, 0.f);
    const float4* wp = reinterpret_cast<const float4*>(Wo + (size_t)hd0 * F) + tid;
#pragma unroll
    for (int f = 0; f < HD / NOC; f++) {
        float4 w4 = wp[(size_t)f * (F / 4)];
#pragma unroll
        for (int b = 0; b < B; b++) {
            float xb = xs[f][b];
            acc[b].x = fmaf(xb, w4.x, acc[b].x);
            acc[b].y = fmaf(xb, w4.y, acc[b].y);
            acc[b].z = fmaf(xb, w4.z, acc[b].z);
            acc[b].w = fmaf(xb, w4.w, acc[b].w);
        }
    }
    float* dst = g_o_part + (size_t)c * B * F;
#pragma unroll
    for (int b = 0; b < B; b++)
        reinterpret_cast<float4*>(dst + b * F)[tid] = acc[b];
}

__global__ __launch_bounds__(256) void oproj_reduce_k(
        const float* __restrict__ bo, float* __restrict__ y) {
    int g = blockIdx.x * 256 + threadIdx.x;   // < B*F
    int b = g >> 10, col = g & 1023;
    float s = 0.f;
#pragma unroll 8
    for (int c = 0; c < NOC; c++)
        s += g_o_part[(size_t)c * B * F + b * F + col];
    y[g] = s + bo[col];
}

// -------- launch --------
extern "C" void kernel_launch(void* const* d_in, const int* in_sizes, int n_in,
                              void* d_out, int out_size) {
    (void)in_sizes; (void)n_in; (void)out_size;
    const float* x    = (const float*)d_in[0];
    const float* kk   = (const float*)d_in[1];
    const float* kv   = (const float*)d_in[2];
    const int*   kvix = (const int*)  d_in[3];
    const float* Wq   = (const float*)d_in[4];
    const float* bq   = (const float*)d_in[5];
    const float* Wk   = (const float*)d_in[6];
    const float* bk   = (const float*)d_in[7];
    const float* Wv   = (const float*)d_in[8];
    const float* bv   = (const float*)d_in[9];
    const float* Wo   = (const float*)d_in[10];
    const float* bo   = (const float*)d_in[11];

    // Output layout (all float32): y[B*F], kv_key[B*L*HD], kv_value[B*L*HD],
    // new_idx[B] stored as float.
    float* out  = (float*)d_out;
    float* y    = out;
    float* okey = out + (size_t)B * F;
    float* oval = okey + (size_t)B * L * HD;
    float* oidx = oval + (size_t)B * L * HD;

    qkv_partial_k<<<dim3(NFC, 3), 256>>>(x, Wq, Wk, Wv);
    qkv_reduce_k<<<(3 * B * HD) / 256, 256>>>(bq, bk, bv, kvix, oidx);
    fused_k_kernel<<<B * (L / TBK), 256>>>(kk, kvix, okey);
    attn_stats_k<<<B * H, 256>>>(kvix);
    fused_v_kernel<<<B * NCV, 256>>>(kv, kvix, oval);
    attn_combine_k<<<(B * HD) / 256, 256>>>();
    oproj_partial_k<<<NOC, 256>>>(Wo);
    oproj_reduce_k<<<(B * F) / 256, 256>>>(bo, y);
}